// round 15
// baseline (speedup 1.0000x reference)
#include <cuda_runtime.h>
#include <math.h>
#include <stdint.h>

#define NN 10000      // nodes / timesteps
#define DD 256        // node features
#define HH 512        // hidden
#define G4 2048       // 4*HH
#define EE 640000     // edges
#define NL 128        // CTAs per LSTM layer
#define LTH 128       // threads per LSTM CTA (4 warps = 4 hidden units)
#define RING 8        // h0 ring depth (layer0 runahead window)

// ---------------- device scratch (static globals; no allocation APIs) ----------------
static __device__ int g_is64;
static __device__ __align__(16) int   g_src[EE];
static __device__ __align__(16) int   g_dst[EE];
static __device__ __align__(16) float g_hsum[NN * DD];           // x + agg
static __device__ __align__(16) float g_a1[NN * HH];             // relu(lin1)
static __device__ __align__(16) float g_hmlp[NN * HH];           // lin2 out
static __device__ __align__(16) float g_hbn[NN * HH];            // bn+relu out (LSTM input)
static __device__ __align__(16) float g_hs1[NN * HH];
static __device__ __align__(16) float g_part[2 * 80 * HH];       // BN partial sums
static __device__ __align__(16) float g_scale[HH];
static __device__ __align__(16) float g_shift[HH];
static __device__ __align__(16) float g_bias0[G4];
static __device__ __align__(16) float g_bias1[G4];
static __device__ __align__(16) float g_hbuf0[RING][HH];         // layer0 h ring buffer
static __device__ __align__(16) float g_hbuf1[2][HH];            // layer1 h double buffer
// counters on separate 128B lines: [0]=bar0, [64]=bar1
static __device__ __align__(128) unsigned g_sync[128];

// ---------------- sync primitives ----------------
__device__ __forceinline__ unsigned ldcg_u32(const unsigned* p) {
    unsigned v;
    asm volatile("ld.global.cg.u32 %0, [%1];" : "=r"(v) : "l"(p) : "memory");
    return v;
}
__device__ __forceinline__ void red_release_gpu_add(unsigned* p, unsigned v) {
    asm volatile("red.release.gpu.global.add.u32 [%0], %1;" :: "l"(p), "r"(v) : "memory");
}
// Warp-cooperative dual-counter wait: all lanes broadcast-load both counters,
// exit together; single acquire fence after success.
__device__ __forceinline__ void warp_wait2(const unsigned* pA, unsigned tA,
                                           const unsigned* pB, unsigned tB) {
    int spin = 0;
    while (1) {
        unsigned a = ldcg_u32(pA);
        unsigned b = ldcg_u32(pB);
        if (__all_sync(0xffffffffu, a >= tA && b >= tB)) break;
        if (++spin > 48) __nanosleep(32);
    }
    asm volatile("fence.acq_rel.gpu;" ::: "memory");
}
__device__ __forceinline__ void warp_wait1(const unsigned* pA, unsigned tA) {
    int spin = 0;
    while (1) {
        unsigned a = ldcg_u32(pA);
        if (__all_sync(0xffffffffu, a >= tA)) break;
        if (++spin > 48) __nanosleep(32);
    }
    asm volatile("fence.acq_rel.gpu;" ::: "memory");
}

// ---------------- edge dtype sniff ----------------
__global__ void k_detect(const int* __restrict__ ei) {
    __shared__ int any;
    if (threadIdx.x == 0) any = 0;
    __syncthreads();
    int v = ei[2 * threadIdx.x + 1];   // 256 odd words; all-zero => int64
    if (v != 0) atomicExch(&any, 1);
    __syncthreads();
    if (threadIdx.x == 0) g_is64 = (any == 0) ? 1 : 0;
}

__global__ void k_norm_edges(const int* __restrict__ ei, int E) {
    int e = blockIdx.x * blockDim.x + threadIdx.x;
    if (e >= E) return;
    if (g_is64) { g_src[e] = ei[2 * e]; g_dst[e] = ei[2 * (E + e)]; }
    else        { g_src[e] = ei[e];     g_dst[e] = ei[E + e]; }
}

// ---------------- agg = x (copy), then scatter-add ----------------
__global__ void k_copy_x(const float4* __restrict__ x4) {
    int i = blockIdx.x * blockDim.x + threadIdx.x;
    if (i < NN * DD / 4) ((float4*)g_hsum)[i] = x4[i];
}

__global__ void k_scatter(const float* __restrict__ x, int E) {
    int id = blockIdx.x * blockDim.x + threadIdx.x;   // E*64 threads, 4 feats each
    if (id >= E * 64) return;
    int e = id >> 6;
    int c = (id & 63) << 2;
    int s = g_src[e], d = g_dst[e];
    float4 v = *(const float4*)(x + (size_t)s * DD + c);
    float* o = g_hsum + (size_t)d * DD + c;
    atomicAdd(o + 0, v.x); atomicAdd(o + 1, v.y);
    atomicAdd(o + 2, v.z); atomicAdd(o + 3, v.w);
}

// ---------------- generic NT GEMM: C[i,j] = sum_k A[i,k]*B[j,k] + bias[j] ----------------
__global__ __launch_bounds__(256)
void k_gemm_nt(const float* __restrict__ A, const float* __restrict__ B,
               const float* __restrict__ bias, float* __restrict__ C,
               int M, int N, int K, int relu) {
    __shared__ float As[16][128];
    __shared__ float Bs[16][128];
    const int i0 = blockIdx.x * 128;
    const int j0 = blockIdx.y * 128;
    const int t  = threadIdx.x;
    const int tx = t & 15, ty = t >> 4;
    float acc[8][8];
#pragma unroll
    for (int r = 0; r < 8; ++r)
#pragma unroll
        for (int c = 0; c < 8; ++c) acc[r][c] = 0.f;

    for (int k0 = 0; k0 < K; k0 += 16) {
#pragma unroll
        for (int q = 0; q < 2; ++q) {
            int chunk = t * 2 + q;              // 0..511
            int row   = chunk >> 2;             // 0..127
            int kc    = (chunk & 3) << 2;       // 0,4,8,12
            float4 va = make_float4(0.f, 0.f, 0.f, 0.f);
            if (i0 + row < M)
                va = *(const float4*)(A + (size_t)(i0 + row) * K + k0 + kc);
            As[kc + 0][row] = va.x; As[kc + 1][row] = va.y;
            As[kc + 2][row] = va.z; As[kc + 3][row] = va.w;
            float4 vb = *(const float4*)(B + (size_t)(j0 + row) * K + k0 + kc);
            Bs[kc + 0][row] = vb.x; Bs[kc + 1][row] = vb.y;
            Bs[kc + 2][row] = vb.z; Bs[kc + 3][row] = vb.w;
        }
        __syncthreads();
#pragma unroll
        for (int k = 0; k < 16; ++k) {
            float4 a0 = *(const float4*)&As[k][ty * 8];
            float4 a1 = *(const float4*)&As[k][ty * 8 + 4];
            float4 b0 = *(const float4*)&Bs[k][tx * 8];
            float4 b1 = *(const float4*)&Bs[k][tx * 8 + 4];
            float a[8] = {a0.x, a0.y, a0.z, a0.w, a1.x, a1.y, a1.z, a1.w};
            float b[8] = {b0.x, b0.y, b0.z, b0.w, b1.x, b1.y, b1.z, b1.w};
#pragma unroll
            for (int r = 0; r < 8; ++r)
#pragma unroll
                for (int c = 0; c < 8; ++c) acc[r][c] += a[r] * b[c];
        }
        __syncthreads();
    }
#pragma unroll
    for (int r = 0; r < 8; ++r) {
        int i = i0 + ty * 8 + r;
        if (i >= M) continue;
        int j = j0 + tx * 8;
        float4 o0, o1;
        float v;
        v = acc[r][0] + bias[j + 0]; o0.x = relu ? fmaxf(v, 0.f) : v;
        v = acc[r][1] + bias[j + 1]; o0.y = relu ? fmaxf(v, 0.f) : v;
        v = acc[r][2] + bias[j + 2]; o0.z = relu ? fmaxf(v, 0.f) : v;
        v = acc[r][3] + bias[j + 3]; o0.w = relu ? fmaxf(v, 0.f) : v;
        v = acc[r][4] + bias[j + 4]; o1.x = relu ? fmaxf(v, 0.f) : v;
        v = acc[r][5] + bias[j + 5]; o1.y = relu ? fmaxf(v, 0.f) : v;
        v = acc[r][6] + bias[j + 6]; o1.z = relu ? fmaxf(v, 0.f) : v;
        v = acc[r][7] + bias[j + 7]; o1.w = relu ? fmaxf(v, 0.f) : v;
        *(float4*)(C + (size_t)i * N + j)     = o0;
        *(float4*)(C + (size_t)i * N + j + 4) = o1;
    }
}

// ---------------- BatchNorm (training-mode batch stats, deterministic 2-stage) ----------------
__global__ void k_bn_part(const float* __restrict__ h) {
    int blk = blockIdx.x;          // 80 blocks * 125 rows = 10000
    int j   = threadIdx.x;         // 512
    int r0  = blk * 125;
    float s = 0.f, ss = 0.f;
    for (int r = 0; r < 125; ++r) {
        float v = h[(size_t)(r0 + r) * HH + j];
        s += v; ss += v * v;
    }
    g_part[blk * HH + j]            = s;
    g_part[80 * HH + blk * HH + j]  = ss;
}

__global__ void k_bn_final(const float* __restrict__ gamma, const float* __restrict__ beta) {
    int j = threadIdx.x;
    float s = 0.f, ss = 0.f;
    for (int b = 0; b < 80; ++b) {
        s  += g_part[b * HH + j];
        ss += g_part[80 * HH + b * HH + j];
    }
    float mean = s * (1.f / NN);
    float var  = ss * (1.f / NN) - mean * mean;
    float rstd = rsqrtf(var + 1e-5f);
    float sc   = rstd * gamma[j];
    g_scale[j] = sc;
    g_shift[j] = beta[j] - mean * sc;
}

__global__ void k_bn_apply(const float* __restrict__ h) {
    int i = blockIdx.x * blockDim.x + threadIdx.x;   // over NN*HH/4
    if (i >= NN * HH / 4) return;
    float4 v  = ((const float4*)h)[i];
    int    j4 = (i & 127) * 4;
    float4 sc = *(const float4*)&g_scale[j4];
    float4 sh = *(const float4*)&g_shift[j4];
    float4 o;
    o.x = fmaxf(v.x * sc.x + sh.x, 0.f);
    o.y = fmaxf(v.y * sc.y + sh.y, 0.f);
    o.z = fmaxf(v.z * sc.z + sh.z, 0.f);
    o.w = fmaxf(v.w * sc.w + sh.w, 0.f);
    ((float4*)g_hbn)[i] = o;
}

__global__ void k_prep_bias(const float* __restrict__ bi0, const float* __restrict__ bh0,
                            const float* __restrict__ bi1, const float* __restrict__ bh1) {
    int i = blockIdx.x * blockDim.x + threadIdx.x;
    if (i < G4) {
        g_bias0[i] = bi0[i] + bh0[i];
        g_bias1[i] = bi1[i] + bh1[i];
    }
}

// ---------------- fused 2-layer LSTM (both input projections folded in) ----------------
__global__ void k_lstm_init() {
    int t = threadIdx.x;
    for (int i = t; i < RING * HH; i += blockDim.x) ((float*)g_hbuf0)[i] = 0.f;
    for (int i = t; i < 2 * HH;    i += blockDim.x) ((float*)g_hbuf1)[i] = 0.f;
    if (t < 128) g_sync[t] = 0u;
}

// Layer0 CTA: W_ih0 + W_hh0 rows in registers; x[t] prefetched from g_hbn.
// Layer1 CTA: W_ih1 + W_hh1 rows in registers; x = h0 from ring.
// bar0/bar1 count completed steps*NL. Waits (per warp, fused dual poll):
//   L0 step s: bar0 >= s*NL; every 4th step also bar1 >= (s-4)*NL (WAR, ring 8).
//   L1 step t: bar1 >= t*NL AND bar0 >= (t+1)*NL.
__global__ __launch_bounds__(LTH, 2)
void k_lstm2(const float* __restrict__ whh0, const float* __restrict__ wih0,
             const float* __restrict__ wih1, const float* __restrict__ whh1,
             float* __restrict__ hs1,
             float* __restrict__ hfin0, float* __restrict__ cfin0,
             float* __restrict__ hfin1, float* __restrict__ cfin1) {
    const int w    = threadIdx.x >> 5;       // warp 0..3 -> hidden unit within CTA
    const int l    = threadIdx.x & 31;
    const bool is1 = blockIdx.x >= NL;
    const int  cid = is1 ? (blockIdx.x - NL) : blockIdx.x;
    const int  m   = cid * 4 + w;            // unit 0..511

    unsigned* bar0 = &g_sync[0];
    unsigned* bar1 = &g_sync[64];

    // Weights in registers: wr[0..3] = input-proj rows, wr[4..7] = recurrent rows.
    float wr[8][4][4];
    {
        const float* wih = is1 ? wih1 : wih0;
        const float* whh = is1 ? whh1 : whh0;
#pragma unroll
        for (int g = 0; g < 4; ++g) {
            const float* rp = wih + (size_t)(g * HH + m) * HH;
#pragma unroll
            for (int c = 0; c < 4; ++c) {
                float4 v = *(const float4*)(rp + c * 128 + l * 4);
                wr[g][c][0] = v.x; wr[g][c][1] = v.y; wr[g][c][2] = v.z; wr[g][c][3] = v.w;
            }
        }
#pragma unroll
        for (int g = 0; g < 4; ++g) {
            const float* rp = whh + (size_t)(g * HH + m) * HH;
#pragma unroll
            for (int c = 0; c < 4; ++c) {
                float4 v = *(const float4*)(rp + c * 128 + l * 4);
                wr[4 + g][c][0] = v.x; wr[4 + g][c][1] = v.y;
                wr[4 + g][c][2] = v.z; wr[4 + g][c][3] = v.w;
            }
        }
    }
    // folded bias (lanes 0..3 hold the 4 gate biases)
    float bv = 0.f;
    if (l < 4) bv = __ldg((is1 ? g_bias1 : g_bias0) + l * HH + m);
    const float bp0 = __shfl_sync(0xffffffffu, bv, 0);
    const float bp1 = __shfl_sync(0xffffffffu, bv, 1);
    const float bp2 = __shfl_sync(0xffffffffu, bv, 2);
    const float bp3 = __shfl_sync(0xffffffffu, bv, 3);

    float cst = 0.f;

    if (!is1) {
        // =========================== LAYER 0 ===========================
        // prefetch x[0]
        float4 xb[4];
#pragma unroll
        for (int c = 0; c < 4; ++c)
            xb[c] = *(const float4*)(g_hbn + c * 128 + l * 4);
        for (int s = 0; s < NN; ++s) {
            // observe (per-warp): peers done step s-1; periodic WAR check vs layer1
            if (s > 0) {
                if ((s & 3) == 0 && s >= RING)
                    warp_wait2(bar0, (unsigned)s * NL, bar1, (unsigned)(s - 4) * NL);
                else
                    warp_wait1(bar0, (unsigned)s * NL);
            }

            const float* hb = g_hbuf0[(s + RING - 1) & (RING - 1)];   // h0[s-1]
            float a0, a1, a2, a3;
            {
                // issue h loads, then overlap x-projection FMAs
                float4 hv0 = __ldcg((const float4*)(hb + 0 * 128 + l * 4));
                float4 hv1 = __ldcg((const float4*)(hb + 1 * 128 + l * 4));
                float4 hv2 = __ldcg((const float4*)(hb + 2 * 128 + l * 4));
                float4 hv3 = __ldcg((const float4*)(hb + 3 * 128 + l * 4));
                a0 = a1 = a2 = a3 = 0.f;
#pragma unroll
                for (int c = 0; c < 4; ++c) {
                    a0 += wr[0][c][0] * xb[c].x + wr[0][c][1] * xb[c].y + wr[0][c][2] * xb[c].z + wr[0][c][3] * xb[c].w;
                    a1 += wr[1][c][0] * xb[c].x + wr[1][c][1] * xb[c].y + wr[1][c][2] * xb[c].z + wr[1][c][3] * xb[c].w;
                    a2 += wr[2][c][0] * xb[c].x + wr[2][c][1] * xb[c].y + wr[2][c][2] * xb[c].z + wr[2][c][3] * xb[c].w;
                    a3 += wr[3][c][0] * xb[c].x + wr[3][c][1] * xb[c].y + wr[3][c][2] * xb[c].z + wr[3][c][3] * xb[c].w;
                }
                float4 hv[4] = {hv0, hv1, hv2, hv3};
#pragma unroll
                for (int c = 0; c < 4; ++c) {
                    a0 += wr[4][c][0] * hv[c].x + wr[4][c][1] * hv[c].y + wr[4][c][2] * hv[c].z + wr[4][c][3] * hv[c].w;
                    a1 += wr[5][c][0] * hv[c].x + wr[5][c][1] * hv[c].y + wr[5][c][2] * hv[c].z + wr[5][c][3] * hv[c].w;
                    a2 += wr[6][c][0] * hv[c].x + wr[6][c][1] * hv[c].y + wr[6][c][2] * hv[c].z + wr[6][c][3] * hv[c].w;
                    a3 += wr[7][c][0] * hv[c].x + wr[7][c][1] * hv[c].y + wr[7][c][2] * hv[c].z + wr[7][c][3] * hv[c].w;
                }
            }
#pragma unroll
            for (int o = 16; o > 0; o >>= 1) {
                a0 += __shfl_xor_sync(0xffffffffu, a0, o);
                a1 += __shfl_xor_sync(0xffffffffu, a1, o);
                a2 += __shfl_xor_sync(0xffffffffu, a2, o);
                a3 += __shfl_xor_sync(0xffffffffu, a3, o);
            }
            float gi = a0 + bp0, gf = a1 + bp1, gg = a2 + bp2, go = a3 + bp3;
            float ii = 1.f / (1.f + __expf(-gi));
            float ff = 1.f / (1.f + __expf(-gf));
            float g_ = tanhf(gg);
            float oo = 1.f / (1.f + __expf(-go));
            cst = ff * cst + ii * g_;
            float hval = oo * tanhf(cst);
            if (l == 0) {
                __stcg(&g_hbuf0[s & (RING - 1)][m], hval);
                if (s == NN - 1) { hfin0[m] = hval; cfin0[m] = cst; }
            }
            // prefetch x[s+1] (off critical path, hidden under barrier)
            if (s + 1 < NN) {
                const float* xp = g_hbn + (size_t)(s + 1) * HH;
#pragma unroll
                for (int c = 0; c < 4; ++c)
                    xb[c] = *(const float4*)(xp + c * 128 + l * 4);
            }
            // arrive: CTA bar orders all warps' h stores before thread0's release-arrival
            __syncthreads();
            if (threadIdx.x == 0) red_release_gpu_add(bar0, 1u);
        }
    } else {
        // =========================== LAYER 1 ===========================
        for (int t = 0; t < NN; ++t) {
            // observe (per-warp, fused): peers done t-1 AND layer0 done t
            warp_wait2(bar1, (unsigned)t * NL, bar0, (unsigned)(t + 1) * NL);

            const float* xbp = g_hbuf0[t & (RING - 1)];   // h0[t]
            const float* hb  = g_hbuf1[(t + 1) & 1];      // h1[t-1]
            float a0 = 0.f, a1 = 0.f, a2 = 0.f, a3 = 0.f;
#pragma unroll
            for (int c = 0; c < 4; ++c) {
                float4 xv = __ldcg((const float4*)(xbp + c * 128 + l * 4));
                float4 hv = __ldcg((const float4*)(hb + c * 128 + l * 4));
                a0 += wr[0][c][0] * xv.x + wr[0][c][1] * xv.y + wr[0][c][2] * xv.z + wr[0][c][3] * xv.w;
                a1 += wr[1][c][0] * xv.x + wr[1][c][1] * xv.y + wr[1][c][2] * xv.z + wr[1][c][3] * xv.w;
                a2 += wr[2][c][0] * xv.x + wr[2][c][1] * xv.y + wr[2][c][2] * xv.z + wr[2][c][3] * xv.w;
                a3 += wr[3][c][0] * xv.x + wr[3][c][1] * xv.y + wr[3][c][2] * xv.z + wr[3][c][3] * xv.w;
                a0 += wr[4][c][0] * hv.x + wr[4][c][1] * hv.y + wr[4][c][2] * hv.z + wr[4][c][3] * hv.w;
                a1 += wr[5][c][0] * hv.x + wr[5][c][1] * hv.y + wr[5][c][2] * hv.z + wr[5][c][3] * hv.w;
                a2 += wr[6][c][0] * hv.x + wr[6][c][1] * hv.y + wr[6][c][2] * hv.z + wr[6][c][3] * hv.w;
                a3 += wr[7][c][0] * hv.x + wr[7][c][1] * hv.y + wr[7][c][2] * hv.z + wr[7][c][3] * hv.w;
            }
#pragma unroll
            for (int o = 16; o > 0; o >>= 1) {
                a0 += __shfl_xor_sync(0xffffffffu, a0, o);
                a1 += __shfl_xor_sync(0xffffffffu, a1, o);
                a2 += __shfl_xor_sync(0xffffffffu, a2, o);
                a3 += __shfl_xor_sync(0xffffffffu, a3, o);
            }
            float gi = a0 + bp0, gf = a1 + bp1, gg = a2 + bp2, go = a3 + bp3;
            float ii = 1.f / (1.f + __expf(-gi));
            float ff = 1.f / (1.f + __expf(-gf));
            float g_ = tanhf(gg);
            float oo = 1.f / (1.f + __expf(-go));
            cst = ff * cst + ii * g_;
            float hval = oo * tanhf(cst);
            if (l == 0) {
                __stcg(&g_hbuf1[t & 1][m], hval);
                hs1[(size_t)t * HH + m] = hval;
                if (t == NN - 1) { hfin1[m] = hval; cfin1[m] = cst; }
            }
            __syncthreads();
            if (threadIdx.x == 0) red_release_gpu_add(bar1, 1u);
        }
    }
}

// ---------------- fc head: out[t] = dot(hs1[t], fc_w) + fc_b ----------------
__global__ void k_fc(const float* __restrict__ hs, const float* __restrict__ fw,
                     const float* __restrict__ fb, float* __restrict__ out) {
    int warp = (blockIdx.x * blockDim.x + threadIdx.x) >> 5;
    int l    = threadIdx.x & 31;
    if (warp >= NN) return;
    const float4* hp = (const float4*)(hs + (size_t)warp * HH);
    const float4* wp = (const float4*)fw;
    float s = 0.f;
#pragma unroll
    for (int c = 0; c < 4; ++c) {
        float4 a = hp[l + c * 32];
        float4 b = wp[l + c * 32];
        s += a.x * b.x + a.y * b.y + a.z * b.z + a.w * b.w;
    }
#pragma unroll
    for (int o = 16; o > 0; o >>= 1) s += __shfl_xor_sync(0xffffffffu, s, o);
    if (l == 0) out[warp] = s + fb[0];
}

// ---------------- launch ----------------
extern "C" void kernel_launch(void* const* d_in, const int* in_sizes, int n_in,
                              void* d_out, int out_size) {
    const float* x     = (const float*)d_in[0];
    const int*   ei    = (const int*)d_in[1];
    const float* w1    = (const float*)d_in[2];
    const float* b1    = (const float*)d_in[3];
    const float* w2    = (const float*)d_in[4];
    const float* b2    = (const float*)d_in[5];
    const float* gamma = (const float*)d_in[6];
    const float* beta  = (const float*)d_in[7];
    const float* wih0  = (const float*)d_in[8];
    const float* whh0  = (const float*)d_in[9];
    const float* bih0  = (const float*)d_in[10];
    const float* bhh0  = (const float*)d_in[11];
    const float* wih1  = (const float*)d_in[12];
    const float* whh1  = (const float*)d_in[13];
    const float* bih1  = (const float*)d_in[14];
    const float* bhh1  = (const float*)d_in[15];
    const float* fcw   = (const float*)d_in[16];
    const float* fcb   = (const float*)d_in[17];
    float* out = (float*)d_out;
    const int E = in_sizes[1] / 2;

    float *p_hsum, *p_a1, *p_hmlp, *p_hs1;
    cudaGetSymbolAddress((void**)&p_hsum, g_hsum);
    cudaGetSymbolAddress((void**)&p_a1,   g_a1);
    cudaGetSymbolAddress((void**)&p_hmlp, g_hmlp);
    cudaGetSymbolAddress((void**)&p_hs1,  g_hs1);

    // 1. edge dtype + normalize
    k_detect<<<1, 256>>>(ei);
    k_norm_edges<<<(E + 255) / 256, 256>>>(ei, E);

    // 2. GIN aggregation: hsum = x + scatter_add(x[src] -> dst)
    k_copy_x<<<(NN * DD / 4 + 255) / 256, 256>>>((const float4*)x);
    k_scatter<<<(E * 64 + 255) / 256, 256>>>(x, E);

    // 3. GIN MLP
    k_gemm_nt<<<dim3(79, 4), 256>>>(p_hsum, w1, b1, p_a1, NN, HH, DD, 1);
    k_gemm_nt<<<dim3(79, 4), 256>>>(p_a1, w2, b2, p_hmlp, NN, HH, HH, 0);

    // 4. BatchNorm + ReLU
    k_bn_part<<<80, 512>>>(p_hmlp);
    k_bn_final<<<1, 512>>>(gamma, beta);
    k_prep_bias<<<8, 256>>>(bih0, bhh0, bih1, bhh1);
    k_bn_apply<<<(NN * HH / 4 + 255) / 256, 256>>>(p_hmlp);

    // 5. Fused 2-layer pipelined persistent LSTM (both input projections in-kernel)
    k_lstm_init<<<1, 1024>>>();
    k_lstm2<<<2 * NL, LTH>>>(whh0, wih0, wih1, whh1, p_hs1,
                             out + 10000, out + 11024,   // h0, c0 finals
                             out + 10512, out + 11536);  // h1, c1 finals

    // 6. fc head
    k_fc<<<1250, 256>>>(p_hs1, fcw, fcb, out);
}

// round 16
// speedup vs baseline: 1.6818x; 1.6818x over previous
#include <cuda_runtime.h>
#include <math.h>
#include <stdint.h>

#define NN 10000      // nodes / timesteps
#define DD 256        // node features
#define HH 512        // hidden
#define G4 2048       // 4*HH
#define EE 640000     // edges
#define NL 128        // CTAs per LSTM layer
#define LTH 128       // threads per LSTM CTA (4 warps = 4 hidden units)
#define RING 4        // h0 ring depth (layer0 runahead window)

// ---------------- device scratch (static globals; no allocation APIs) ----------------
static __device__ int g_is64;
static __device__ __align__(16) int   g_src[EE];
static __device__ __align__(16) int   g_dst[EE];
static __device__ __align__(16) float g_hsum[NN * DD];           // x + agg
static __device__ __align__(16) float g_a1[NN * HH];             // relu(lin1)
static __device__ __align__(16) float g_hmlp[NN * HH];           // lin2 out
static __device__ __align__(16) float g_hbn[NN * HH];            // bn+relu out (LSTM input)
static __device__ __align__(16) float g_hs1[NN * HH];
static __device__ __align__(16) float g_part[2 * 80 * HH];       // BN partial sums
static __device__ __align__(16) float g_scale[HH];
static __device__ __align__(16) float g_shift[HH];
static __device__ __align__(16) float g_bias0[G4];
static __device__ __align__(16) float g_bias1[G4];
static __device__ __align__(16) float g_hbuf0[RING][HH];         // layer0 h ring buffer
static __device__ __align__(16) float g_hbuf1[2][HH];            // layer1 h double buffer
static __device__ unsigned g_bar0;
static __device__ unsigned g_bar1;

// ---------------- sync primitives (R6-frozen) ----------------
__device__ __forceinline__ unsigned ld_acquire_gpu(const unsigned* p) {
    unsigned v;
    asm volatile("ld.acquire.gpu.global.u32 %0, [%1];" : "=r"(v) : "l"(p) : "memory");
    return v;
}
__device__ __forceinline__ void red_release_gpu_add(unsigned* p, unsigned v) {
    asm volatile("red.release.gpu.global.add.u32 [%0], %1;" :: "l"(p), "r"(v) : "memory");
}
__device__ __forceinline__ void wait_ge(const unsigned* p, unsigned tgt) {
    int spin = 0;
    while (ld_acquire_gpu(p) < tgt) {
        if (++spin > 96) __nanosleep(32);
    }
}

// ---------------- edge dtype sniff ----------------
__global__ void k_detect(const int* __restrict__ ei) {
    __shared__ int any;
    if (threadIdx.x == 0) any = 0;
    __syncthreads();
    int v = ei[2 * threadIdx.x + 1];   // 256 odd words; all-zero => int64
    if (v != 0) atomicExch(&any, 1);
    __syncthreads();
    if (threadIdx.x == 0) g_is64 = (any == 0) ? 1 : 0;
}

__global__ void k_norm_edges(const int* __restrict__ ei, int E) {
    int e = blockIdx.x * blockDim.x + threadIdx.x;
    if (e >= E) return;
    if (g_is64) { g_src[e] = ei[2 * e]; g_dst[e] = ei[2 * (E + e)]; }
    else        { g_src[e] = ei[e];     g_dst[e] = ei[E + e]; }
}

// ---------------- agg = x (copy), then scatter-add ----------------
__global__ void k_copy_x(const float4* __restrict__ x4) {
    int i = blockIdx.x * blockDim.x + threadIdx.x;
    if (i < NN * DD / 4) ((float4*)g_hsum)[i] = x4[i];
}

__global__ void k_scatter(const float* __restrict__ x, int E) {
    int id = blockIdx.x * blockDim.x + threadIdx.x;   // E*64 threads, 4 feats each
    if (id >= E * 64) return;
    int e = id >> 6;
    int c = (id & 63) << 2;
    int s = g_src[e], d = g_dst[e];
    float4 v = *(const float4*)(x + (size_t)s * DD + c);
    float* o = g_hsum + (size_t)d * DD + c;
    atomicAdd(o + 0, v.x); atomicAdd(o + 1, v.y);
    atomicAdd(o + 2, v.z); atomicAdd(o + 3, v.w);
}

// ---------------- generic NT GEMM: C[i,j] = sum_k A[i,k]*B[j,k] + bias[j] ----------------
__global__ __launch_bounds__(256)
void k_gemm_nt(const float* __restrict__ A, const float* __restrict__ B,
               const float* __restrict__ bias, float* __restrict__ C,
               int M, int N, int K, int relu) {
    __shared__ float As[16][128];
    __shared__ float Bs[16][128];
    const int i0 = blockIdx.x * 128;
    const int j0 = blockIdx.y * 128;
    const int t  = threadIdx.x;
    const int tx = t & 15, ty = t >> 4;
    float acc[8][8];
#pragma unroll
    for (int r = 0; r < 8; ++r)
#pragma unroll
        for (int c = 0; c < 8; ++c) acc[r][c] = 0.f;

    for (int k0 = 0; k0 < K; k0 += 16) {
#pragma unroll
        for (int q = 0; q < 2; ++q) {
            int chunk = t * 2 + q;              // 0..511
            int row   = chunk >> 2;             // 0..127
            int kc    = (chunk & 3) << 2;       // 0,4,8,12
            float4 va = make_float4(0.f, 0.f, 0.f, 0.f);
            if (i0 + row < M)
                va = *(const float4*)(A + (size_t)(i0 + row) * K + k0 + kc);
            As[kc + 0][row] = va.x; As[kc + 1][row] = va.y;
            As[kc + 2][row] = va.z; As[kc + 3][row] = va.w;
            float4 vb = *(const float4*)(B + (size_t)(j0 + row) * K + k0 + kc);
            Bs[kc + 0][row] = vb.x; Bs[kc + 1][row] = vb.y;
            Bs[kc + 2][row] = vb.z; Bs[kc + 3][row] = vb.w;
        }
        __syncthreads();
#pragma unroll
        for (int k = 0; k < 16; ++k) {
            float4 a0 = *(const float4*)&As[k][ty * 8];
            float4 a1 = *(const float4*)&As[k][ty * 8 + 4];
            float4 b0 = *(const float4*)&Bs[k][tx * 8];
            float4 b1 = *(const float4*)&Bs[k][tx * 8 + 4];
            float a[8] = {a0.x, a0.y, a0.z, a0.w, a1.x, a1.y, a1.z, a1.w};
            float b[8] = {b0.x, b0.y, b0.z, b0.w, b1.x, b1.y, b1.z, b1.w};
#pragma unroll
            for (int r = 0; r < 8; ++r)
#pragma unroll
                for (int c = 0; c < 8; ++c) acc[r][c] += a[r] * b[c];
        }
        __syncthreads();
    }
#pragma unroll
    for (int r = 0; r < 8; ++r) {
        int i = i0 + ty * 8 + r;
        if (i >= M) continue;
        int j = j0 + tx * 8;
        float4 o0, o1;
        float v;
        v = acc[r][0] + bias[j + 0]; o0.x = relu ? fmaxf(v, 0.f) : v;
        v = acc[r][1] + bias[j + 1]; o0.y = relu ? fmaxf(v, 0.f) : v;
        v = acc[r][2] + bias[j + 2]; o0.z = relu ? fmaxf(v, 0.f) : v;
        v = acc[r][3] + bias[j + 3]; o0.w = relu ? fmaxf(v, 0.f) : v;
        v = acc[r][4] + bias[j + 4]; o1.x = relu ? fmaxf(v, 0.f) : v;
        v = acc[r][5] + bias[j + 5]; o1.y = relu ? fmaxf(v, 0.f) : v;
        v = acc[r][6] + bias[j + 6]; o1.z = relu ? fmaxf(v, 0.f) : v;
        v = acc[r][7] + bias[j + 7]; o1.w = relu ? fmaxf(v, 0.f) : v;
        *(float4*)(C + (size_t)i * N + j)     = o0;
        *(float4*)(C + (size_t)i * N + j + 4) = o1;
    }
}

// ---------------- BatchNorm (training-mode batch stats, deterministic 2-stage) ----------------
__global__ void k_bn_part(const float* __restrict__ h) {
    int blk = blockIdx.x;          // 80 blocks * 125 rows = 10000
    int j   = threadIdx.x;         // 512
    int r0  = blk * 125;
    float s = 0.f, ss = 0.f;
    for (int r = 0; r < 125; ++r) {
        float v = h[(size_t)(r0 + r) * HH + j];
        s += v; ss += v * v;
    }
    g_part[blk * HH + j]            = s;
    g_part[80 * HH + blk * HH + j]  = ss;
}

__global__ void k_bn_final(const float* __restrict__ gamma, const float* __restrict__ beta) {
    int j = threadIdx.x;
    float s = 0.f, ss = 0.f;
    for (int b = 0; b < 80; ++b) {
        s  += g_part[b * HH + j];
        ss += g_part[80 * HH + b * HH + j];
    }
    float mean = s * (1.f / NN);
    float var  = ss * (1.f / NN) - mean * mean;
    float rstd = rsqrtf(var + 1e-5f);
    float sc   = rstd * gamma[j];
    g_scale[j] = sc;
    g_shift[j] = beta[j] - mean * sc;
}

__global__ void k_bn_apply(const float* __restrict__ h) {
    int i = blockIdx.x * blockDim.x + threadIdx.x;   // over NN*HH/4
    if (i >= NN * HH / 4) return;
    float4 v  = ((const float4*)h)[i];
    int    j4 = (i & 127) * 4;
    float4 sc = *(const float4*)&g_scale[j4];
    float4 sh = *(const float4*)&g_shift[j4];
    float4 o;
    o.x = fmaxf(v.x * sc.x + sh.x, 0.f);
    o.y = fmaxf(v.y * sc.y + sh.y, 0.f);
    o.z = fmaxf(v.z * sc.z + sh.z, 0.f);
    o.w = fmaxf(v.w * sc.w + sh.w, 0.f);
    ((float4*)g_hbn)[i] = o;
}

__global__ void k_prep_bias(const float* __restrict__ bi0, const float* __restrict__ bh0,
                            const float* __restrict__ bi1, const float* __restrict__ bh1) {
    int i = blockIdx.x * blockDim.x + threadIdx.x;
    if (i < G4) {
        g_bias0[i] = bi0[i] + bh0[i];
        g_bias1[i] = bi1[i] + bh1[i];
    }
}

// ---------------- fused 2-layer LSTM (R6 barrier, projections folded) ----------------
__global__ void k_lstm_init() {
    int t = threadIdx.x;
    for (int i = t; i < RING * HH; i += blockDim.x) ((float*)g_hbuf0)[i] = 0.f;
    for (int i = t; i < 2 * HH;    i += blockDim.x) ((float*)g_hbuf1)[i] = 0.f;
    if (t == 0) { g_bar0 = 0u; g_bar1 = 0u; }
}

__global__ __launch_bounds__(LTH, 2)
void k_lstm2(const float* __restrict__ whh0, const float* __restrict__ wih0,
             const float* __restrict__ wih1, const float* __restrict__ whh1,
             float* __restrict__ hs1,
             float* __restrict__ hfin0, float* __restrict__ cfin0,
             float* __restrict__ hfin1, float* __restrict__ cfin1) {
    const int w    = threadIdx.x >> 5;       // warp 0..3 -> hidden unit within CTA
    const int l    = threadIdx.x & 31;
    const bool is1 = blockIdx.x >= NL;
    const int  m   = (is1 ? (blockIdx.x - NL) : blockIdx.x) * 4 + w;   // unit 0..511

    // Weights in registers: wr[0..3] = input-proj rows (W_ih), wr[4..7] = recurrent rows (W_hh)
    float wr[8][4][4];
    {
        const float* wih = is1 ? wih1 : wih0;
        const float* whh = is1 ? whh1 : whh0;
#pragma unroll
        for (int g = 0; g < 4; ++g) {
            const float* rp = wih + (size_t)(g * HH + m) * HH;
#pragma unroll
            for (int c = 0; c < 4; ++c) {
                float4 v = *(const float4*)(rp + c * 128 + l * 4);
                wr[g][c][0] = v.x; wr[g][c][1] = v.y; wr[g][c][2] = v.z; wr[g][c][3] = v.w;
            }
        }
#pragma unroll
        for (int g = 0; g < 4; ++g) {
            const float* rp = whh + (size_t)(g * HH + m) * HH;
#pragma unroll
            for (int c = 0; c < 4; ++c) {
                float4 v = *(const float4*)(rp + c * 128 + l * 4);
                wr[4 + g][c][0] = v.x; wr[4 + g][c][1] = v.y;
                wr[4 + g][c][2] = v.z; wr[4 + g][c][3] = v.w;
            }
        }
    }
    // folded bias (lanes 0..3 hold the 4 gate biases)
    float bv = 0.f;
    if (l < 4) bv = __ldg((is1 ? g_bias1 : g_bias0) + l * HH + m);
    const float bp0 = __shfl_sync(0xffffffffu, bv, 0);
    const float bp1 = __shfl_sync(0xffffffffu, bv, 1);
    const float bp2 = __shfl_sync(0xffffffffu, bv, 2);
    const float bp3 = __shfl_sync(0xffffffffu, bv, 3);

    float cst = 0.f;

    if (!is1) {
        // =========================== LAYER 0 ===========================
        // prefetch x[0] into registers
        float4 xb[4];
#pragma unroll
        for (int c = 0; c < 4; ++c)
            xb[c] = *(const float4*)(g_hbn + c * 128 + l * 4);
        for (int s = 0; s < NN; ++s) {
            // R6 barrier: thread0 acquire-polls, syncthreads broadcasts
            if (threadIdx.x == 0) {
                wait_ge(&g_bar0, (unsigned)s * NL);
                if (s >= RING) wait_ge(&g_bar1, (unsigned)(s - (RING - 1)) * NL);
            }
            __syncthreads();

            const float* hb = g_hbuf0[(s + RING - 1) & (RING - 1)];   // h0[s-1]
            // issue h loads, overlap x-projection FMAs (x already in regs)
            float4 hv0 = __ldcg((const float4*)(hb + 0 * 128 + l * 4));
            float4 hv1 = __ldcg((const float4*)(hb + 1 * 128 + l * 4));
            float4 hv2 = __ldcg((const float4*)(hb + 2 * 128 + l * 4));
            float4 hv3 = __ldcg((const float4*)(hb + 3 * 128 + l * 4));
            float a0 = 0.f, a1 = 0.f, a2 = 0.f, a3 = 0.f;
#pragma unroll
            for (int c = 0; c < 4; ++c) {
                a0 += wr[0][c][0] * xb[c].x + wr[0][c][1] * xb[c].y + wr[0][c][2] * xb[c].z + wr[0][c][3] * xb[c].w;
                a1 += wr[1][c][0] * xb[c].x + wr[1][c][1] * xb[c].y + wr[1][c][2] * xb[c].z + wr[1][c][3] * xb[c].w;
                a2 += wr[2][c][0] * xb[c].x + wr[2][c][1] * xb[c].y + wr[2][c][2] * xb[c].z + wr[2][c][3] * xb[c].w;
                a3 += wr[3][c][0] * xb[c].x + wr[3][c][1] * xb[c].y + wr[3][c][2] * xb[c].z + wr[3][c][3] * xb[c].w;
            }
            {
                float4 hv[4] = {hv0, hv1, hv2, hv3};
#pragma unroll
                for (int c = 0; c < 4; ++c) {
                    a0 += wr[4][c][0] * hv[c].x + wr[4][c][1] * hv[c].y + wr[4][c][2] * hv[c].z + wr[4][c][3] * hv[c].w;
                    a1 += wr[5][c][0] * hv[c].x + wr[5][c][1] * hv[c].y + wr[5][c][2] * hv[c].z + wr[5][c][3] * hv[c].w;
                    a2 += wr[6][c][0] * hv[c].x + wr[6][c][1] * hv[c].y + wr[6][c][2] * hv[c].z + wr[6][c][3] * hv[c].w;
                    a3 += wr[7][c][0] * hv[c].x + wr[7][c][1] * hv[c].y + wr[7][c][2] * hv[c].z + wr[7][c][3] * hv[c].w;
                }
            }
#pragma unroll
            for (int o = 16; o > 0; o >>= 1) {
                a0 += __shfl_xor_sync(0xffffffffu, a0, o);
                a1 += __shfl_xor_sync(0xffffffffu, a1, o);
                a2 += __shfl_xor_sync(0xffffffffu, a2, o);
                a3 += __shfl_xor_sync(0xffffffffu, a3, o);
            }
            float gi = a0 + bp0, gf = a1 + bp1, gg = a2 + bp2, go = a3 + bp3;
            float ii = 1.f / (1.f + __expf(-gi));
            float ff = 1.f / (1.f + __expf(-gf));
            float g_ = tanhf(gg);
            float oo = 1.f / (1.f + __expf(-go));
            cst = ff * cst + ii * g_;
            float hval = oo * tanhf(cst);
            if (l == 0) {
                __stcg(&g_hbuf0[s & (RING - 1)][m], hval);
                if (s == NN - 1) { hfin0[m] = hval; cfin0[m] = cst; }
            }
            // prefetch x[s+1] (off critical path, hidden under next barrier wait)
            if (s + 1 < NN) {
                const float* xp = g_hbn + (size_t)(s + 1) * HH;
#pragma unroll
                for (int c = 0; c < 4; ++c)
                    xb[c] = *(const float4*)(xp + c * 128 + l * 4);
            }
            // arrive (R6): CTA bar orders h stores before thread0's release-arrival
            __syncthreads();
            if (threadIdx.x == 0) red_release_gpu_add(&g_bar0, 1u);
        }
    } else {
        // =========================== LAYER 1 ===========================
        for (int t = 0; t < NN; ++t) {
            if (threadIdx.x == 0) {
                wait_ge(&g_bar1, (unsigned)t * NL);
                wait_ge(&g_bar0, (unsigned)(t + 1) * NL);
            }
            __syncthreads();

            const float* xbp = g_hbuf0[t & (RING - 1)];   // h0[t]
            const float* hb  = g_hbuf1[(t + 1) & 1];      // h1[t-1]
            float a0 = 0.f, a1 = 0.f, a2 = 0.f, a3 = 0.f;
#pragma unroll
            for (int c = 0; c < 4; ++c) {
                float4 xv = __ldcg((const float4*)(xbp + c * 128 + l * 4));
                float4 hv = __ldcg((const float4*)(hb + c * 128 + l * 4));
                a0 += wr[0][c][0] * xv.x + wr[0][c][1] * xv.y + wr[0][c][2] * xv.z + wr[0][c][3] * xv.w;
                a1 += wr[1][c][0] * xv.x + wr[1][c][1] * xv.y + wr[1][c][2] * xv.z + wr[1][c][3] * xv.w;
                a2 += wr[2][c][0] * xv.x + wr[2][c][1] * xv.y + wr[2][c][2] * xv.z + wr[2][c][3] * xv.w;
                a3 += wr[3][c][0] * xv.x + wr[3][c][1] * xv.y + wr[3][c][2] * xv.z + wr[3][c][3] * xv.w;
                a0 += wr[4][c][0] * hv.x + wr[4][c][1] * hv.y + wr[4][c][2] * hv.z + wr[4][c][3] * hv.w;
                a1 += wr[5][c][0] * hv.x + wr[5][c][1] * hv.y + wr[5][c][2] * hv.z + wr[5][c][3] * hv.w;
                a2 += wr[6][c][0] * hv.x + wr[6][c][1] * hv.y + wr[6][c][2] * hv.z + wr[6][c][3] * hv.w;
                a3 += wr[7][c][0] * hv.x + wr[7][c][1] * hv.y + wr[7][c][2] * hv.z + wr[7][c][3] * hv.w;
            }
#pragma unroll
            for (int o = 16; o > 0; o >>= 1) {
                a0 += __shfl_xor_sync(0xffffffffu, a0, o);
                a1 += __shfl_xor_sync(0xffffffffu, a1, o);
                a2 += __shfl_xor_sync(0xffffffffu, a2, o);
                a3 += __shfl_xor_sync(0xffffffffu, a3, o);
            }
            float gi = a0 + bp0, gf = a1 + bp1, gg = a2 + bp2, go = a3 + bp3;
            float ii = 1.f / (1.f + __expf(-gi));
            float ff = 1.f / (1.f + __expf(-gf));
            float g_ = tanhf(gg);
            float oo = 1.f / (1.f + __expf(-go));
            cst = ff * cst + ii * g_;
            float hval = oo * tanhf(cst);
            if (l == 0) {
                __stcg(&g_hbuf1[t & 1][m], hval);
                hs1[(size_t)t * HH + m] = hval;
                if (t == NN - 1) { hfin1[m] = hval; cfin1[m] = cst; }
            }
            __syncthreads();
            if (threadIdx.x == 0) red_release_gpu_add(&g_bar1, 1u);
        }
    }
}

// ---------------- fc head: out[t] = dot(hs1[t], fc_w) + fc_b ----------------
__global__ void k_fc(const float* __restrict__ hs, const float* __restrict__ fw,
                     const float* __restrict__ fb, float* __restrict__ out) {
    int warp = (blockIdx.x * blockDim.x + threadIdx.x) >> 5;
    int l    = threadIdx.x & 31;
    if (warp >= NN) return;
    const float4* hp = (const float4*)(hs + (size_t)warp * HH);
    const float4* wp = (const float4*)fw;
    float s = 0.f;
#pragma unroll
    for (int c = 0; c < 4; ++c) {
        float4 a = hp[l + c * 32];
        float4 b = wp[l + c * 32];
        s += a.x * b.x + a.y * b.y + a.z * b.z + a.w * b.w;
    }
#pragma unroll
    for (int o = 16; o > 0; o >>= 1) s += __shfl_xor_sync(0xffffffffu, s, o);
    if (l == 0) out[warp] = s + fb[0];
}

// ---------------- launch ----------------
extern "C" void kernel_launch(void* const* d_in, const int* in_sizes, int n_in,
                              void* d_out, int out_size) {
    const float* x     = (const float*)d_in[0];
    const int*   ei    = (const int*)d_in[1];
    const float* w1    = (const float*)d_in[2];
    const float* b1    = (const float*)d_in[3];
    const float* w2    = (const float*)d_in[4];
    const float* b2    = (const float*)d_in[5];
    const float* gamma = (const float*)d_in[6];
    const float* beta  = (const float*)d_in[7];
    const float* wih0  = (const float*)d_in[8];
    const float* whh0  = (const float*)d_in[9];
    const float* bih0  = (const float*)d_in[10];
    const float* bhh0  = (const float*)d_in[11];
    const float* wih1  = (const float*)d_in[12];
    const float* whh1  = (const float*)d_in[13];
    const float* bih1  = (const float*)d_in[14];
    const float* bhh1  = (const float*)d_in[15];
    const float* fcw   = (const float*)d_in[16];
    const float* fcb   = (const float*)d_in[17];
    float* out = (float*)d_out;
    const int E = in_sizes[1] / 2;

    float *p_hsum, *p_a1, *p_hmlp, *p_hs1;
    cudaGetSymbolAddress((void**)&p_hsum, g_hsum);
    cudaGetSymbolAddress((void**)&p_a1,   g_a1);
    cudaGetSymbolAddress((void**)&p_hmlp, g_hmlp);
    cudaGetSymbolAddress((void**)&p_hs1,  g_hs1);

    // 1. edge dtype + normalize
    k_detect<<<1, 256>>>(ei);
    k_norm_edges<<<(E + 255) / 256, 256>>>(ei, E);

    // 2. GIN aggregation: hsum = x + scatter_add(x[src] -> dst)
    k_copy_x<<<(NN * DD / 4 + 255) / 256, 256>>>((const float4*)x);
    k_scatter<<<(E * 64 + 255) / 256, 256>>>(x, E);

    // 3. GIN MLP
    k_gemm_nt<<<dim3(79, 4), 256>>>(p_hsum, w1, b1, p_a1, NN, HH, DD, 1);
    k_gemm_nt<<<dim3(79, 4), 256>>>(p_a1, w2, b2, p_hmlp, NN, HH, HH, 0);

    // 4. BatchNorm + ReLU
    k_bn_part<<<80, 512>>>(p_hmlp);
    k_bn_final<<<1, 512>>>(gamma, beta);
    k_prep_bias<<<8, 256>>>(bih0, bhh0, bih1, bhh1);
    k_bn_apply<<<(NN * HH / 4 + 255) / 256, 256>>>(p_hmlp);

    // 5. Fused 2-layer pipelined persistent LSTM (R6 barrier, projections folded)
    k_lstm_init<<<1, 1024>>>();
    k_lstm2<<<2 * NL, LTH>>>(whh0, wih0, wih1, whh1, p_hs1,
                             out + 10000, out + 11024,   // h0, c0 finals
                             out + 10512, out + 11536);  // h1, c1 finals

    // 6. fc head
    k_fc<<<1250, 256>>>(p_hs1, fcw, fcb, out);
}

// round 17
// speedup vs baseline: 1.9577x; 1.1641x over previous
#include <cuda_runtime.h>
#include <math.h>
#include <stdint.h>

#define NN 10000      // nodes / timesteps
#define DD 256        // node features
#define HH 512        // hidden
#define G4 2048       // 4*HH
#define EE 640000     // edges
#define NL 128        // CTAs per LSTM layer
#define LTH 128       // threads per LSTM CTA (4 warps = 4 hidden units)
#define RING 4        // h0 ring depth (layer0 runahead window)

// ---------------- device scratch (static globals; no allocation APIs) ----------------
static __device__ int g_is64;
static __device__ __align__(16) int   g_src[EE];
static __device__ __align__(16) int   g_dst[EE];
static __device__ __align__(16) float g_hsum[NN * DD];           // x + agg
static __device__ __align__(16) float g_a1[NN * HH];             // relu(lin1)
static __device__ __align__(16) float g_hmlp[NN * HH];           // lin2 out
static __device__ __align__(16) float g_hbn[NN * HH];            // bn+relu out (LSTM input)
static __device__ __align__(16) float g_pre[(size_t)NN * G4];    // LSTM L0 input projection
static __device__ __align__(16) float g_hs1[NN * HH];
static __device__ __align__(16) float g_part[2 * 80 * HH];       // BN partial sums
static __device__ __align__(16) float g_scale[HH];
static __device__ __align__(16) float g_shift[HH];
static __device__ __align__(16) float g_bias0[G4];
static __device__ __align__(16) float g_bias1[G4];
static __device__ __align__(16) float g_hbuf0[RING][HH];         // layer0 h ring buffer
static __device__ __align__(16) float g_hbuf1[2][HH];            // layer1 h double buffer
static __device__ unsigned g_bar0;
static __device__ unsigned g_bar1;

// ---------------- sync primitives (R6-frozen) ----------------
__device__ __forceinline__ unsigned ld_acquire_gpu(const unsigned* p) {
    unsigned v;
    asm volatile("ld.acquire.gpu.global.u32 %0, [%1];" : "=r"(v) : "l"(p) : "memory");
    return v;
}
__device__ __forceinline__ void red_release_gpu_add(unsigned* p, unsigned v) {
    asm volatile("red.release.gpu.global.add.u32 [%0], %1;" :: "l"(p), "r"(v) : "memory");
}
__device__ __forceinline__ void wait_ge(const unsigned* p, unsigned tgt) {
    int spin = 0;
    while (ld_acquire_gpu(p) < tgt) {
        if (++spin > 96) __nanosleep(32);
    }
}

// ---------------- edge dtype sniff ----------------
__global__ void k_detect(const int* __restrict__ ei) {
    __shared__ int any;
    if (threadIdx.x == 0) any = 0;
    __syncthreads();
    int v = ei[2 * threadIdx.x + 1];   // 256 odd words; all-zero => int64
    if (v != 0) atomicExch(&any, 1);
    __syncthreads();
    if (threadIdx.x == 0) g_is64 = (any == 0) ? 1 : 0;
}

__global__ void k_norm_edges(const int* __restrict__ ei, int E) {
    int e = blockIdx.x * blockDim.x + threadIdx.x;
    if (e >= E) return;
    if (g_is64) { g_src[e] = ei[2 * e]; g_dst[e] = ei[2 * (E + e)]; }
    else        { g_src[e] = ei[e];     g_dst[e] = ei[E + e]; }
}

// ---------------- agg = x (copy), then scatter-add ----------------
__global__ void k_copy_x(const float4* __restrict__ x4) {
    int i = blockIdx.x * blockDim.x + threadIdx.x;
    if (i < NN * DD / 4) ((float4*)g_hsum)[i] = x4[i];
}

__global__ void k_scatter(const float* __restrict__ x, int E) {
    int id = blockIdx.x * blockDim.x + threadIdx.x;   // E*64 threads, 4 feats each
    if (id >= E * 64) return;
    int e = id >> 6;
    int c = (id & 63) << 2;
    int s = g_src[e], d = g_dst[e];
    float4 v = *(const float4*)(x + (size_t)s * DD + c);
    float* o = g_hsum + (size_t)d * DD + c;
    atomicAdd(o + 0, v.x); atomicAdd(o + 1, v.y);
    atomicAdd(o + 2, v.z); atomicAdd(o + 3, v.w);
}

// ---------------- generic NT GEMM: C[i,j] = sum_k A[i,k]*B[j,k] + bias[j] ----------------
__global__ __launch_bounds__(256)
void k_gemm_nt(const float* __restrict__ A, const float* __restrict__ B,
               const float* __restrict__ bias, float* __restrict__ C,
               int M, int N, int K, int relu) {
    __shared__ float As[16][128];
    __shared__ float Bs[16][128];
    const int i0 = blockIdx.x * 128;
    const int j0 = blockIdx.y * 128;
    const int t  = threadIdx.x;
    const int tx = t & 15, ty = t >> 4;
    float acc[8][8];
#pragma unroll
    for (int r = 0; r < 8; ++r)
#pragma unroll
        for (int c = 0; c < 8; ++c) acc[r][c] = 0.f;

    for (int k0 = 0; k0 < K; k0 += 16) {
#pragma unroll
        for (int q = 0; q < 2; ++q) {
            int chunk = t * 2 + q;              // 0..511
            int row   = chunk >> 2;             // 0..127
            int kc    = (chunk & 3) << 2;       // 0,4,8,12
            float4 va = make_float4(0.f, 0.f, 0.f, 0.f);
            if (i0 + row < M)
                va = *(const float4*)(A + (size_t)(i0 + row) * K + k0 + kc);
            As[kc + 0][row] = va.x; As[kc + 1][row] = va.y;
            As[kc + 2][row] = va.z; As[kc + 3][row] = va.w;
            float4 vb = *(const float4*)(B + (size_t)(j0 + row) * K + k0 + kc);
            Bs[kc + 0][row] = vb.x; Bs[kc + 1][row] = vb.y;
            Bs[kc + 2][row] = vb.z; Bs[kc + 3][row] = vb.w;
        }
        __syncthreads();
#pragma unroll
        for (int k = 0; k < 16; ++k) {
            float4 a0 = *(const float4*)&As[k][ty * 8];
            float4 a1 = *(const float4*)&As[k][ty * 8 + 4];
            float4 b0 = *(const float4*)&Bs[k][tx * 8];
            float4 b1 = *(const float4*)&Bs[k][tx * 8 + 4];
            float a[8] = {a0.x, a0.y, a0.z, a0.w, a1.x, a1.y, a1.z, a1.w};
            float b[8] = {b0.x, b0.y, b0.z, b0.w, b1.x, b1.y, b1.z, b1.w};
#pragma unroll
            for (int r = 0; r < 8; ++r)
#pragma unroll
                for (int c = 0; c < 8; ++c) acc[r][c] += a[r] * b[c];
        }
        __syncthreads();
    }
#pragma unroll
    for (int r = 0; r < 8; ++r) {
        int i = i0 + ty * 8 + r;
        if (i >= M) continue;
        int j = j0 + tx * 8;
        float4 o0, o1;
        float v;
        v = acc[r][0] + bias[j + 0]; o0.x = relu ? fmaxf(v, 0.f) : v;
        v = acc[r][1] + bias[j + 1]; o0.y = relu ? fmaxf(v, 0.f) : v;
        v = acc[r][2] + bias[j + 2]; o0.z = relu ? fmaxf(v, 0.f) : v;
        v = acc[r][3] + bias[j + 3]; o0.w = relu ? fmaxf(v, 0.f) : v;
        v = acc[r][4] + bias[j + 4]; o1.x = relu ? fmaxf(v, 0.f) : v;
        v = acc[r][5] + bias[j + 5]; o1.y = relu ? fmaxf(v, 0.f) : v;
        v = acc[r][6] + bias[j + 6]; o1.z = relu ? fmaxf(v, 0.f) : v;
        v = acc[r][7] + bias[j + 7]; o1.w = relu ? fmaxf(v, 0.f) : v;
        *(float4*)(C + (size_t)i * N + j)     = o0;
        *(float4*)(C + (size_t)i * N + j + 4) = o1;
    }
}

// ---------------- BatchNorm (training-mode batch stats, deterministic 2-stage) ----------------
__global__ void k_bn_part(const float* __restrict__ h) {
    int blk = blockIdx.x;          // 80 blocks * 125 rows = 10000
    int j   = threadIdx.x;         // 512
    int r0  = blk * 125;
    float s = 0.f, ss = 0.f;
    for (int r = 0; r < 125; ++r) {
        float v = h[(size_t)(r0 + r) * HH + j];
        s += v; ss += v * v;
    }
    g_part[blk * HH + j]            = s;
    g_part[80 * HH + blk * HH + j]  = ss;
}

__global__ void k_bn_final(const float* __restrict__ gamma, const float* __restrict__ beta) {
    int j = threadIdx.x;
    float s = 0.f, ss = 0.f;
    for (int b = 0; b < 80; ++b) {
        s  += g_part[b * HH + j];
        ss += g_part[80 * HH + b * HH + j];
    }
    float mean = s * (1.f / NN);
    float var  = ss * (1.f / NN) - mean * mean;
    float rstd = rsqrtf(var + 1e-5f);
    float sc   = rstd * gamma[j];
    g_scale[j] = sc;
    g_shift[j] = beta[j] - mean * sc;
}

__global__ void k_bn_apply(const float* __restrict__ h) {
    int i = blockIdx.x * blockDim.x + threadIdx.x;   // over NN*HH/4
    if (i >= NN * HH / 4) return;
    float4 v  = ((const float4*)h)[i];
    int    j4 = (i & 127) * 4;
    float4 sc = *(const float4*)&g_scale[j4];
    float4 sh = *(const float4*)&g_shift[j4];
    float4 o;
    o.x = fmaxf(v.x * sc.x + sh.x, 0.f);
    o.y = fmaxf(v.y * sc.y + sh.y, 0.f);
    o.z = fmaxf(v.z * sc.z + sh.z, 0.f);
    o.w = fmaxf(v.w * sc.w + sh.w, 0.f);
    ((float4*)g_hbn)[i] = o;
}

__global__ void k_prep_bias(const float* __restrict__ bi0, const float* __restrict__ bh0,
                            const float* __restrict__ bi1, const float* __restrict__ bh1) {
    int i = blockIdx.x * blockDim.x + threadIdx.x;
    if (i < G4) {
        g_bias0[i] = bi0[i] + bh0[i];
        g_bias1[i] = bi1[i] + bh1[i];
    }
}

// ---------------- fused 2-layer LSTM (R6 barrier + smem-staged h broadcast) ----------------
__global__ void k_lstm_init() {
    int t = threadIdx.x;
    for (int i = t; i < RING * HH; i += blockDim.x) ((float*)g_hbuf0)[i] = 0.f;
    for (int i = t; i < 2 * HH;    i += blockDim.x) ((float*)g_hbuf1)[i] = 0.f;
    if (t == 0) { g_bar0 = 0u; g_bar1 = 0u; }
}

__global__ __launch_bounds__(LTH, 2)
void k_lstm2(const float* __restrict__ pre, const float* __restrict__ whh0,
             const float* __restrict__ wih1, const float* __restrict__ whh1,
             float* __restrict__ hs1,
             float* __restrict__ hfin0, float* __restrict__ cfin0,
             float* __restrict__ hfin1, float* __restrict__ cfin1) {
    const int w    = threadIdx.x >> 5;       // warp 0..3 -> hidden unit within CTA
    const int l    = threadIdx.x & 31;
    const bool is1 = blockIdx.x >= NL;
    const int  m   = (is1 ? (blockIdx.x - NL) : blockIdx.x) * 4 + w;   // unit 0..511

    // smem staging: [0:512) = primary h buffer; [512:1024) = second (layer1 only)
    __shared__ __align__(16) float sh[1024];

    // Weights in registers.
    // layer0: wr[0..3] = W_hh0 gate rows for unit m
    // layer1: wr[0..3] = W_ih1 rows, wr[4..7] = W_hh1 rows
    float wr[8][4][4];
#pragma unroll
    for (int g = 0; g < 4; ++g) {
        const float* rp0 = (is1 ? wih1 : whh0) + (size_t)(g * HH + m) * HH;
#pragma unroll
        for (int c = 0; c < 4; ++c) {
            float4 v = *(const float4*)(rp0 + c * 128 + l * 4);
            wr[g][c][0] = v.x; wr[g][c][1] = v.y; wr[g][c][2] = v.z; wr[g][c][3] = v.w;
        }
    }
    if (is1) {
#pragma unroll
        for (int g = 0; g < 4; ++g) {
            const float* rp1 = whh1 + (size_t)(g * HH + m) * HH;
#pragma unroll
            for (int c = 0; c < 4; ++c) {
                float4 v = *(const float4*)(rp1 + c * 128 + l * 4);
                wr[4 + g][c][0] = v.x; wr[4 + g][c][1] = v.y;
                wr[4 + g][c][2] = v.z; wr[4 + g][c][3] = v.w;
            }
        }
    }

    float cst = 0.f;

    if (!is1) {
        // =========================== LAYER 0 ===========================
        float pv = 0.f;
        if (l < 4) pv = __ldg(pre + l * HH + m);          // pre[0]
        for (int s = 0; s < NN; ++s) {
            if (threadIdx.x == 0) {
                wait_ge(&g_bar0, (unsigned)s * NL);
                if (s >= RING) wait_ge(&g_bar1, (unsigned)(s - (RING - 1)) * NL);
            }
            __syncthreads();

            // stage h0[s-1]: each warp loads its 512B quarter (4x fewer L2 requests)
            const float* hb = g_hbuf0[(s + RING - 1) & (RING - 1)];
            {
                float4 v = __ldcg((const float4*)(hb + w * 128 + l * 4));
                *(float4*)(sh + w * 128 + l * 4) = v;
            }
            __syncthreads();

            float a0 = 0.f, a1 = 0.f, a2 = 0.f, a3 = 0.f;
#pragma unroll
            for (int c = 0; c < 4; ++c) {
                float4 hv = *(const float4*)(sh + c * 128 + l * 4);
                a0 += wr[0][c][0] * hv.x + wr[0][c][1] * hv.y + wr[0][c][2] * hv.z + wr[0][c][3] * hv.w;
                a1 += wr[1][c][0] * hv.x + wr[1][c][1] * hv.y + wr[1][c][2] * hv.z + wr[1][c][3] * hv.w;
                a2 += wr[2][c][0] * hv.x + wr[2][c][1] * hv.y + wr[2][c][2] * hv.z + wr[2][c][3] * hv.w;
                a3 += wr[3][c][0] * hv.x + wr[3][c][1] * hv.y + wr[3][c][2] * hv.z + wr[3][c][3] * hv.w;
            }
#pragma unroll
            for (int o = 16; o > 0; o >>= 1) {
                a0 += __shfl_xor_sync(0xffffffffu, a0, o);
                a1 += __shfl_xor_sync(0xffffffffu, a1, o);
                a2 += __shfl_xor_sync(0xffffffffu, a2, o);
                a3 += __shfl_xor_sync(0xffffffffu, a3, o);
            }
            float p0 = __shfl_sync(0xffffffffu, pv, 0);
            float p1 = __shfl_sync(0xffffffffu, pv, 1);
            float p2 = __shfl_sync(0xffffffffu, pv, 2);
            float p3 = __shfl_sync(0xffffffffu, pv, 3);
            float gi = a0 + p0, gf = a1 + p1, gg = a2 + p2, go = a3 + p3;
            float ii = 1.f / (1.f + __expf(-gi));
            float ff = 1.f / (1.f + __expf(-gf));
            float g_ = tanhf(gg);
            float oo = 1.f / (1.f + __expf(-go));
            cst = ff * cst + ii * g_;
            float hval = oo * tanhf(cst);
            if (l == 0) {
                __stcg(&g_hbuf0[s & (RING - 1)][m], hval);
                if (s == NN - 1) { hfin0[m] = hval; cfin0[m] = cst; }
            }
            // prefetch next pre (off critical path)
            float pvn = 0.f;
            if (l < 4 && s + 1 < NN) pvn = __ldg(pre + (size_t)(s + 1) * G4 + l * HH + m);
            pv = pvn;
            __syncthreads();
            if (threadIdx.x == 0) red_release_gpu_add(&g_bar0, 1u);
        }
    } else {
        // =========================== LAYER 1 ===========================
        float bias1v = 0.f;
        if (l < 4) bias1v = __ldg(g_bias1 + l * HH + m);
        const float b1p0 = __shfl_sync(0xffffffffu, bias1v, 0);
        const float b1p1 = __shfl_sync(0xffffffffu, bias1v, 1);
        const float b1p2 = __shfl_sync(0xffffffffu, bias1v, 2);
        const float b1p3 = __shfl_sync(0xffffffffu, bias1v, 3);
        for (int t = 0; t < NN; ++t) {
            if (threadIdx.x == 0) {
                wait_ge(&g_bar1, (unsigned)t * NL);
                wait_ge(&g_bar0, (unsigned)(t + 1) * NL);
            }
            __syncthreads();

            // stage h0[t] and h1[t-1]: each warp loads its quarter of both
            const float* xbp = g_hbuf0[t & (RING - 1)];
            const float* hbp = g_hbuf1[(t + 1) & 1];
            {
                float4 vx = __ldcg((const float4*)(xbp + w * 128 + l * 4));
                float4 vh = __ldcg((const float4*)(hbp + w * 128 + l * 4));
                *(float4*)(sh + w * 128 + l * 4)       = vx;
                *(float4*)(sh + 512 + w * 128 + l * 4) = vh;
            }
            __syncthreads();

            float a0 = 0.f, a1 = 0.f, a2 = 0.f, a3 = 0.f;
#pragma unroll
            for (int c = 0; c < 4; ++c) {
                float4 xv = *(const float4*)(sh + c * 128 + l * 4);
                float4 hv = *(const float4*)(sh + 512 + c * 128 + l * 4);
                a0 += wr[0][c][0] * xv.x + wr[0][c][1] * xv.y + wr[0][c][2] * xv.z + wr[0][c][3] * xv.w;
                a1 += wr[1][c][0] * xv.x + wr[1][c][1] * xv.y + wr[1][c][2] * xv.z + wr[1][c][3] * xv.w;
                a2 += wr[2][c][0] * xv.x + wr[2][c][1] * xv.y + wr[2][c][2] * xv.z + wr[2][c][3] * xv.w;
                a3 += wr[3][c][0] * xv.x + wr[3][c][1] * xv.y + wr[3][c][2] * xv.z + wr[3][c][3] * xv.w;
                a0 += wr[4][c][0] * hv.x + wr[4][c][1] * hv.y + wr[4][c][2] * hv.z + wr[4][c][3] * hv.w;
                a1 += wr[5][c][0] * hv.x + wr[5][c][1] * hv.y + wr[5][c][2] * hv.z + wr[5][c][3] * hv.w;
                a2 += wr[6][c][0] * hv.x + wr[6][c][1] * hv.y + wr[6][c][2] * hv.z + wr[6][c][3] * hv.w;
                a3 += wr[7][c][0] * hv.x + wr[7][c][1] * hv.y + wr[7][c][2] * hv.z + wr[7][c][3] * hv.w;
            }
#pragma unroll
            for (int o = 16; o > 0; o >>= 1) {
                a0 += __shfl_xor_sync(0xffffffffu, a0, o);
                a1 += __shfl_xor_sync(0xffffffffu, a1, o);
                a2 += __shfl_xor_sync(0xffffffffu, a2, o);
                a3 += __shfl_xor_sync(0xffffffffu, a3, o);
            }
            float gi = a0 + b1p0, gf = a1 + b1p1, gg = a2 + b1p2, go = a3 + b1p3;
            float ii = 1.f / (1.f + __expf(-gi));
            float ff = 1.f / (1.f + __expf(-gf));
            float g_ = tanhf(gg);
            float oo = 1.f / (1.f + __expf(-go));
            cst = ff * cst + ii * g_;
            float hval = oo * tanhf(cst);
            if (l == 0) {
                __stcg(&g_hbuf1[t & 1][m], hval);
                hs1[(size_t)t * HH + m] = hval;
                if (t == NN - 1) { hfin1[m] = hval; cfin1[m] = cst; }
            }
            __syncthreads();
            if (threadIdx.x == 0) red_release_gpu_add(&g_bar1, 1u);
        }
    }
}

// ---------------- fc head: out[t] = dot(hs1[t], fc_w) + fc_b ----------------
__global__ void k_fc(const float* __restrict__ hs, const float* __restrict__ fw,
                     const float* __restrict__ fb, float* __restrict__ out) {
    int warp = (blockIdx.x * blockDim.x + threadIdx.x) >> 5;
    int l    = threadIdx.x & 31;
    if (warp >= NN) return;
    const float4* hp = (const float4*)(hs + (size_t)warp * HH);
    const float4* wp = (const float4*)fw;
    float s = 0.f;
#pragma unroll
    for (int c = 0; c < 4; ++c) {
        float4 a = hp[l + c * 32];
        float4 b = wp[l + c * 32];
        s += a.x * b.x + a.y * b.y + a.z * b.z + a.w * b.w;
    }
#pragma unroll
    for (int o = 16; o > 0; o >>= 1) s += __shfl_xor_sync(0xffffffffu, s, o);
    if (l == 0) out[warp] = s + fb[0];
}

// ---------------- launch ----------------
extern "C" void kernel_launch(void* const* d_in, const int* in_sizes, int n_in,
                              void* d_out, int out_size) {
    const float* x     = (const float*)d_in[0];
    const int*   ei    = (const int*)d_in[1];
    const float* w1    = (const float*)d_in[2];
    const float* b1    = (const float*)d_in[3];
    const float* w2    = (const float*)d_in[4];
    const float* b2    = (const float*)d_in[5];
    const float* gamma = (const float*)d_in[6];
    const float* beta  = (const float*)d_in[7];
    const float* wih0  = (const float*)d_in[8];
    const float* whh0  = (const float*)d_in[9];
    const float* bih0  = (const float*)d_in[10];
    const float* bhh0  = (const float*)d_in[11];
    const float* wih1  = (const float*)d_in[12];
    const float* whh1  = (const float*)d_in[13];
    const float* bih1  = (const float*)d_in[14];
    const float* bhh1  = (const float*)d_in[15];
    const float* fcw   = (const float*)d_in[16];
    const float* fcb   = (const float*)d_in[17];
    float* out = (float*)d_out;
    const int E = in_sizes[1] / 2;

    float *p_hsum, *p_a1, *p_hmlp, *p_hbn, *p_pre, *p_hs1, *p_b0;
    cudaGetSymbolAddress((void**)&p_hsum, g_hsum);
    cudaGetSymbolAddress((void**)&p_a1,   g_a1);
    cudaGetSymbolAddress((void**)&p_hmlp, g_hmlp);
    cudaGetSymbolAddress((void**)&p_hbn,  g_hbn);
    cudaGetSymbolAddress((void**)&p_pre,  g_pre);
    cudaGetSymbolAddress((void**)&p_hs1,  g_hs1);
    cudaGetSymbolAddress((void**)&p_b0,   g_bias0);

    // 1. edge dtype + normalize
    k_detect<<<1, 256>>>(ei);
    k_norm_edges<<<(E + 255) / 256, 256>>>(ei, E);

    // 2. GIN aggregation: hsum = x + scatter_add(x[src] -> dst)
    k_copy_x<<<(NN * DD / 4 + 255) / 256, 256>>>((const float4*)x);
    k_scatter<<<(E * 64 + 255) / 256, 256>>>(x, E);

    // 3. GIN MLP
    k_gemm_nt<<<dim3(79, 4), 256>>>(p_hsum, w1, b1, p_a1, NN, HH, DD, 1);
    k_gemm_nt<<<dim3(79, 4), 256>>>(p_a1, w2, b2, p_hmlp, NN, HH, HH, 0);

    // 4. BatchNorm + ReLU
    k_bn_part<<<80, 512>>>(p_hmlp);
    k_bn_final<<<1, 512>>>(gamma, beta);
    k_prep_bias<<<8, 256>>>(bih0, bhh0, bih1, bhh1);
    k_bn_apply<<<(NN * HH / 4 + 255) / 256, 256>>>(p_hmlp);

    // 5. LSTM layer0 input projection GEMM
    k_gemm_nt<<<dim3(79, 16), 256>>>(p_hbn, wih0, p_b0, p_pre, NN, G4, HH, 0);

    // 6. Fused 2-layer pipelined persistent LSTM (R6 barrier + smem staging)
    k_lstm_init<<<1, 1024>>>();
    k_lstm2<<<2 * NL, LTH>>>(p_pre, whh0, wih1, whh1, p_hs1,
                             out + 10000, out + 11024,   // h0, c0 finals
                             out + 10512, out + 11536);  // h1, c1 finals

    // 7. fc head
    k_fc<<<1250, 256>>>(p_hs1, fcw, fcb, out);
}